// round 2
// baseline (speedup 1.0000x reference)
#include <cuda_runtime.h>

// Shapes fixed by the problem
#define BB 16
#define XL 1024
#define YL 1024
#define DD 1024

#define NEG_INF (-1e20f)

// Tiling
#define BM 128
#define BN 128
#define BK 16

// ---------------------------------------------------------------------------
// Kernel 1: scores[b,x,y] = sum_d xs[b,x,d] * ys[b,y,d]   (NT GEMM)
// masked store: mask_ys[b,y]==0 -> NEG_INF
// ---------------------------------------------------------------------------
__global__ __launch_bounds__(256, 2)
void scores_kernel(const float* __restrict__ xs,
                   const float* __restrict__ ys,
                   const int* __restrict__ mask,
                   float* __restrict__ w)
{
    __shared__ float As[BK][BM + 4];
    __shared__ float Bs[BK][BN + 4];

    const int b = blockIdx.z;
    const int rowBase = blockIdx.y * BM;   // x
    const int colBase = blockIdx.x * BN;   // y

    const float* A  = xs + (size_t)b * XL * DD + (size_t)rowBase * DD;
    const float* Bp = ys + (size_t)b * YL * DD + (size_t)colBase * DD;

    const int t  = threadIdx.x;      // 0..255
    const int tx = t & 15;
    const int ty = t >> 4;

    float acc[8][8];
#pragma unroll
    for (int i = 0; i < 8; ++i)
#pragma unroll
        for (int j = 0; j < 8; ++j) acc[i][j] = 0.0f;

    for (int k0 = 0; k0 < DD; k0 += BK) {
        // Load 128x16 tiles of A and B (K-contiguous), scatter transposed.
#pragma unroll
        for (int i = 0; i < 2; ++i) {
            int f  = t + i * 256;    // 0..511 float4 slots
            int r  = f >> 2;         // 0..127 row
            int c4 = f & 3;          // float4 within the 16-wide K slice
            float4 va = *reinterpret_cast<const float4*>(A  + (size_t)r * DD + k0 + c4 * 4);
            float4 vb = *reinterpret_cast<const float4*>(Bp + (size_t)r * DD + k0 + c4 * 4);
            As[c4 * 4 + 0][r] = va.x; As[c4 * 4 + 1][r] = va.y;
            As[c4 * 4 + 2][r] = va.z; As[c4 * 4 + 3][r] = va.w;
            Bs[c4 * 4 + 0][r] = vb.x; Bs[c4 * 4 + 1][r] = vb.y;
            Bs[c4 * 4 + 2][r] = vb.z; Bs[c4 * 4 + 3][r] = vb.w;
        }
        __syncthreads();

#pragma unroll
        for (int k = 0; k < BK; ++k) {
            float4 a0 = *reinterpret_cast<const float4*>(&As[k][ty * 8]);
            float4 a1 = *reinterpret_cast<const float4*>(&As[k][ty * 8 + 4]);
            float4 b0 = *reinterpret_cast<const float4*>(&Bs[k][tx * 8]);
            float4 b1 = *reinterpret_cast<const float4*>(&Bs[k][tx * 8 + 4]);
            float af[8] = {a0.x, a0.y, a0.z, a0.w, a1.x, a1.y, a1.z, a1.w};
            float bf[8] = {b0.x, b0.y, b0.z, b0.w, b1.x, b1.y, b1.z, b1.w};
#pragma unroll
            for (int i = 0; i < 8; ++i)
#pragma unroll
                for (int j = 0; j < 8; ++j)
                    acc[i][j] = fmaf(af[i], bf[j], acc[i][j]);
        }
        __syncthreads();
    }

    // Masked epilogue store
    int msk[8];
#pragma unroll
    for (int j = 0; j < 8; ++j)
        msk[j] = mask[b * YL + colBase + tx * 8 + j];

    float* wrow = w + (size_t)b * XL * YL + (size_t)(rowBase + ty * 8) * YL + colBase + tx * 8;
#pragma unroll
    for (int i = 0; i < 8; ++i) {
        float4 o0, o1;
        o0.x = msk[0] ? acc[i][0] : NEG_INF;
        o0.y = msk[1] ? acc[i][1] : NEG_INF;
        o0.z = msk[2] ? acc[i][2] : NEG_INF;
        o0.w = msk[3] ? acc[i][3] : NEG_INF;
        o1.x = msk[4] ? acc[i][4] : NEG_INF;
        o1.y = msk[5] ? acc[i][5] : NEG_INF;
        o1.z = msk[6] ? acc[i][6] : NEG_INF;
        o1.w = msk[7] ? acc[i][7] : NEG_INF;
        *reinterpret_cast<float4*>(wrow + (size_t)i * YL)     = o0;
        *reinterpret_cast<float4*>(wrow + (size_t)i * YL + 4) = o1;
    }
}

// ---------------------------------------------------------------------------
// Kernel 2: in-place row softmax over YL=1024, one block (256 thr) per row
// ---------------------------------------------------------------------------
__global__ __launch_bounds__(256)
void softmax_kernel(float* __restrict__ w)
{
    __shared__ float red[256];
    const int row = blockIdx.x;                 // 0 .. B*XL-1
    float* p = w + (size_t)row * YL;
    const int t = threadIdx.x;

    float4 v = reinterpret_cast<float4*>(p)[t]; // 4 contiguous per thread

    float m = fmaxf(fmaxf(v.x, v.y), fmaxf(v.z, v.w));
    red[t] = m;
    __syncthreads();
    for (int s = 128; s > 0; s >>= 1) {
        if (t < s) red[t] = fmaxf(red[t], red[t + s]);
        __syncthreads();
    }
    m = red[0];
    __syncthreads();

    float e0 = expf(v.x - m);
    float e1 = expf(v.y - m);
    float e2 = expf(v.z - m);
    float e3 = expf(v.w - m);

    red[t] = e0 + e1 + e2 + e3;
    __syncthreads();
    for (int s = 128; s > 0; s >>= 1) {
        if (t < s) red[t] += red[t + s];
        __syncthreads();
    }
    float inv = 1.0f / red[0];

    float4 o;
    o.x = e0 * inv; o.y = e1 * inv; o.z = e2 * inv; o.w = e3 * inv;
    reinterpret_cast<float4*>(p)[t] = o;
}

// ---------------------------------------------------------------------------
// Kernel 3: emb[b,x,d] = sum_y w[b,x,y] * ys[b,y,d]   (NN GEMM)
// ---------------------------------------------------------------------------
__global__ __launch_bounds__(256, 2)
void emb_kernel(const float* __restrict__ w,
                const float* __restrict__ ys,
                float* __restrict__ emb)
{
    __shared__ float As[BK][BM + 4];
    __shared__ float Bs[BK][BN + 4];

    const int b = blockIdx.z;
    const int rowBase = blockIdx.y * BM;   // x
    const int colBase = blockIdx.x * BN;   // d

    const float* A  = w  + (size_t)b * XL * YL + (size_t)rowBase * YL;
    const float* Bp = ys + (size_t)b * YL * DD;

    const int t  = threadIdx.x;
    const int tx = t & 15;
    const int ty = t >> 4;

    float acc[8][8];
#pragma unroll
    for (int i = 0; i < 8; ++i)
#pragma unroll
        for (int j = 0; j < 8; ++j) acc[i][j] = 0.0f;

    for (int k0 = 0; k0 < YL; k0 += BK) {
        // A tile: 128 rows x 16 K (K contiguous) -> transpose scatter
#pragma unroll
        for (int i = 0; i < 2; ++i) {
            int f  = t + i * 256;
            int r  = f >> 2;
            int c4 = f & 3;
            float4 va = *reinterpret_cast<const float4*>(A + (size_t)r * YL + k0 + c4 * 4);
            As[c4 * 4 + 0][r] = va.x; As[c4 * 4 + 1][r] = va.y;
            As[c4 * 4 + 2][r] = va.z; As[c4 * 4 + 3][r] = va.w;
        }
        // B tile: 16 K-rows x 128 N (N contiguous) -> direct copy
#pragma unroll
        for (int i = 0; i < 2; ++i) {
            int f  = t + i * 256;     // 0..511 float4 slots
            int r  = f >> 5;          // 0..15 K-row
            int c4 = f & 31;          // float4 within 128-wide N
            float4 vb = *reinterpret_cast<const float4*>(
                Bp + (size_t)(k0 + r) * DD + colBase + c4 * 4);
            *reinterpret_cast<float4*>(&Bs[r][c4 * 4]) = vb;
        }
        __syncthreads();

#pragma unroll
        for (int k = 0; k < BK; ++k) {
            float4 a0 = *reinterpret_cast<const float4*>(&As[k][ty * 8]);
            float4 a1 = *reinterpret_cast<const float4*>(&As[k][ty * 8 + 4]);
            float4 b0 = *reinterpret_cast<const float4*>(&Bs[k][tx * 8]);
            float4 b1 = *reinterpret_cast<const float4*>(&Bs[k][tx * 8 + 4]);
            float af[8] = {a0.x, a0.y, a0.z, a0.w, a1.x, a1.y, a1.z, a1.w};
            float bf[8] = {b0.x, b0.y, b0.z, b0.w, b1.x, b1.y, b1.z, b1.w};
#pragma unroll
            for (int i = 0; i < 8; ++i)
#pragma unroll
                for (int j = 0; j < 8; ++j)
                    acc[i][j] = fmaf(af[i], bf[j], acc[i][j]);
        }
        __syncthreads();
    }

    float* crow = emb + (size_t)b * XL * DD + (size_t)(rowBase + ty * 8) * DD + colBase + tx * 8;
#pragma unroll
    for (int i = 0; i < 8; ++i) {
        float4 o0, o1;
        o0.x = acc[i][0]; o0.y = acc[i][1]; o0.z = acc[i][2]; o0.w = acc[i][3];
        o1.x = acc[i][4]; o1.y = acc[i][5]; o1.z = acc[i][6]; o1.w = acc[i][7];
        *reinterpret_cast<float4*>(crow + (size_t)i * DD)     = o0;
        *reinterpret_cast<float4*>(crow + (size_t)i * DD + 4) = o1;
    }
}

// ---------------------------------------------------------------------------
extern "C" void kernel_launch(void* const* d_in, const int* in_sizes, int n_in,
                              void* d_out, int out_size)
{
    const float* xs   = (const float*)d_in[0];
    const float* ys   = (const float*)d_in[1];
    const int*   mask = (const int*)d_in[2];

    float* emb = (float*)d_out;                                  // [B, XL, D]
    float* w   = (float*)d_out + (size_t)BB * XL * DD;           // [B, XL, YL]

    dim3 block(256);
    dim3 gridS(YL / BN, XL / BM, BB);
    scores_kernel<<<gridS, block>>>(xs, ys, mask, w);

    softmax_kernel<<<BB * XL, block>>>(w);

    dim3 gridE(DD / BN, XL / BM, BB);
    emb_kernel<<<gridE, block>>>(w, ys, emb);
}